// round 9
// baseline (speedup 1.0000x reference)
#include <cuda_runtime.h>
#include <cuda_fp16.h>
#include <stdint.h>
#include <math.h>

#define MAXN 131072
#define PAD  8          // one float per 32B L2 sector for atomic targets
#define NBLK_THREADS 1024

__device__ float  g_h[MAXN];            // x @ W                  [N]
__device__ float  g_dinv[MAXN];         // rsqrt(deg+1)           [N]
__device__ __half g_ph[MAXN];           // fp16 p = dinv*h        [N]
__device__ float  g_deg8[MAXN * PAD];   // sector-padded degree   (zeroed in phase 2)
__device__ float  g_acc8[MAXN * PAD];   // sector-padded scatter  (zeroed in phase 4)

// sense-reversing grid barrier (requires all blocks resident: 1 block/SM)
__device__ unsigned g_bar_count = 0;
__device__ unsigned g_bar_gen   = 0;

__device__ __forceinline__ void grid_barrier(unsigned nblocks) {
    __syncthreads();
    if (threadIdx.x == 0) {
        __threadfence();
        volatile unsigned* vgen = &g_bar_gen;
        unsigned gen = *vgen;
        if (atomicAdd(&g_bar_count, 1u) == nblocks - 1u) {
            atomicExch(&g_bar_count, 0u);
            atomicAdd(&g_bar_gen, 1u);
        } else {
            while (*vgen == gen) { }
        }
        __threadfence();
    }
    __syncthreads();
}

// ---------------------------------------------------------------------------
// ONE persistent kernel, 1 block/SM, 1024 threads.
//   Phase 1 (warp-specialized): warps 0-15 compute h=x@W (DRAM stream);
//                               warps 16-31 degree histogram (LTS atomics).
//   Phase 2: dinv = rsqrt(deg+1); ph = fp16(dinv*h); zero deg bins.
//   Phase 3: stage full ph into SMEM (200KB); scatter acc[dst] += ph[src].
//   Phase 4: out = softplus(dinv*(acc + dinv*h) + b); zero acc bins.
// ---------------------------------------------------------------------------
__global__ void __launch_bounds__(NBLK_THREADS, 1)
gcn_mega(const float* __restrict__ x,
         const float* __restrict__ W,
         const int*   __restrict__ src,
         const int*   __restrict__ dst,
         const float* __restrict__ b,
         float* __restrict__ out,
         int N, int C, int E, unsigned nblocks) {
    extern __shared__ __half sph[];

    int tid  = threadIdx.x;
    int wid  = tid >> 5;
    int lane = tid & 31;

    // ---------------- Phase 1: warp-specialized A (dots) || B (histogram) ---
    if (wid < 16) {
        // A: one warp per row, grid-stride over rows
        const float4* w4 = reinterpret_cast<const float4*>(W);
        float4 b0 = __ldg(&w4[lane]);
        float4 b1 = __ldg(&w4[lane + 32]);

        int row    = blockIdx.x * 16 + wid;
        int rstride = nblocks * 16;
        for (; row < N; row += rstride) {
            const float4* xr = reinterpret_cast<const float4*>(x + (size_t)row * C);
            float4 a0 = xr[lane];
            float4 a1 = xr[lane + 32];
            float s = a0.x * b0.x + a0.y * b0.y + a0.z * b0.z + a0.w * b0.w
                    + a1.x * b1.x + a1.y * b1.y + a1.z * b1.z + a1.w * b1.w;
            #pragma unroll
            for (int off = 16; off > 0; off >>= 1)
                s += __shfl_xor_sync(0xffffffffu, s, off);
            if (lane == 0) g_h[row] = s;
        }
    } else {
        // B: degree histogram over dst
        int etid   = blockIdx.x * 512 + (tid - 512);
        int estride = nblocks * 512;
        for (int i = etid; i < E; i += estride)
            atomicAdd(&g_deg8[(unsigned)dst[i] * PAD], 1.0f);
    }

    grid_barrier(nblocks);

    // ---------------- Phase 2: dinv, ph; zero deg bins ----------------------
    {
        int i = blockIdx.x * NBLK_THREADS + tid;
        int stride = nblocks * NBLK_THREADS;
        for (; i < N; i += stride) {
            float d = g_deg8[(unsigned)i * PAD];
            g_deg8[(unsigned)i * PAD] = 0.0f;
            float dinv = rsqrtf(d + 1.0f);
            g_dinv[i] = dinv;
            g_ph[i] = __float2half_rn(dinv * g_h[i]);
        }
    }

    grid_barrier(nblocks);

    // ---------------- Phase 3: stage ph -> SMEM; scatter --------------------
    {
        int n16 = (N * 2 + 15) / 16;   // uint4 count (MAXN padding makes over-read safe)
        const uint4* gp4 = reinterpret_cast<const uint4*>(g_ph);
        uint4* sp4 = reinterpret_cast<uint4*>(sph);
        for (int i = tid; i < n16; i += NBLK_THREADS)
            sp4[i] = gp4[i];
        __syncthreads();

        int i = blockIdx.x * NBLK_THREADS + tid;
        int stride = nblocks * NBLK_THREADS;
        for (; i < E; i += stride) {
            int s = src[i];
            int d = dst[i];
            atomicAdd(&g_acc8[(unsigned)d * PAD], __half2float(sph[s]));
        }
    }

    grid_barrier(nblocks);

    // ---------------- Phase 4: epilogue; zero acc bins ----------------------
    {
        float bb = b[0];
        int i = blockIdx.x * NBLK_THREADS + tid;
        int stride = nblocks * NBLK_THREADS;
        for (; i < N; i += stride) {
            float a = g_acc8[(unsigned)i * PAD];
            g_acc8[(unsigned)i * PAD] = 0.0f;
            float q = g_dinv[i];
            float v = q * (a + q * g_h[i]) + bb;
            out[i] = fmaxf(v, 0.0f) + log1pf(expf(-fabsf(v)));
        }
    }
}

extern "C" void kernel_launch(void* const* d_in, const int* in_sizes, int n_in,
                              void* d_out, int out_size) {
    const float* x   = (const float*)d_in[0];
    const int*   ei  = (const int*)d_in[1];   // [2, E], int32
    const float* W   = (const float*)d_in[2];
    const float* b   = (const float*)d_in[3];
    float*       out = (float*)d_out;

    int C = in_sizes[2];            // 256
    int N = in_sizes[0] / C;        // 100000
    int E = in_sizes[1] / 2;        // 3200000

    const int* src = ei;
    const int* dst = ei + E;

    int sm_count = 148;
    cudaDeviceGetAttribute(&sm_count, cudaDevAttrMultiProcessorCount, 0);

    size_t smem_bytes = ((size_t)N * 2 + 15) & ~(size_t)15;  // fp16 p vector
    static int attr_set = 0;
    if (!attr_set) {
        cudaFuncSetAttribute(gcn_mega,
                             cudaFuncAttributeMaxDynamicSharedMemorySize,
                             227 * 1024);
        attr_set = 1;
    }

    gcn_mega<<<sm_count, NBLK_THREADS, smem_bytes>>>(
        x, W, src, dst, b, out, N, C, E, (unsigned)sm_count);
}

// round 10
// speedup vs baseline: 2.4926x; 2.4926x over previous
#include <cuda_runtime.h>
#include <cuda_fp16.h>
#include <stdint.h>
#include <math.h>

#define MAXN 131072
#define PAD  8   // one float per 32B L2 sector for atomic targets

__device__ float  g_h[MAXN];            // x @ W                  [N]
__device__ float  g_dinv[MAXN];         // rsqrt(deg+1)           [N]
__device__ __half g_ph[MAXN];           // fp16 p = dinv*h        [N]
__device__ float  g_deg8[MAXN * PAD];   // sector-padded degree   (zeroed after use)
__device__ float  g_acc8[MAXN * PAD];   // sector-padded scatter  (zeroed after use)

// ---------------------------------------------------------------------------
// K1 (fused): per-warp row dot products, 2 rows/warp (ILP), streaming loads
// + grid-stride degree histogram into sector-padded bins (LTS atomics).
// ---------------------------------------------------------------------------
__global__ void k1_fused(const float* __restrict__ x,
                         const float* __restrict__ W,
                         const int*   __restrict__ dst,
                         int N, int C, int E) {
    int tid  = blockIdx.x * blockDim.x + threadIdx.x;
    int warp = tid >> 5;
    int lane = tid & 31;

    int r0 = warp * 2;
    int r1 = r0 + 1;

    if (r0 < N) {
        const float4* w4 = reinterpret_cast<const float4*>(W);
        float4 b0 = __ldg(&w4[lane]);
        float4 b1 = __ldg(&w4[lane + 32]);

        const float4* xr0 = reinterpret_cast<const float4*>(x + (size_t)r0 * C);
        float4 a0 = __ldcs(&xr0[lane]);
        float4 a1 = __ldcs(&xr0[lane + 32]);

        float s0 = a0.x * b0.x + a0.y * b0.y + a0.z * b0.z + a0.w * b0.w
                 + a1.x * b1.x + a1.y * b1.y + a1.z * b1.z + a1.w * b1.w;

        float s1 = 0.0f;
        if (r1 < N) {
            const float4* xr1 = reinterpret_cast<const float4*>(x + (size_t)r1 * C);
            float4 c0 = __ldcs(&xr1[lane]);
            float4 c1 = __ldcs(&xr1[lane + 32]);
            s1 = c0.x * b0.x + c0.y * b0.y + c0.z * b0.z + c0.w * b0.w
               + c1.x * b1.x + c1.y * b1.y + c1.z * b1.z + c1.w * b1.w;
        }

        #pragma unroll
        for (int off = 16; off > 0; off >>= 1) {
            s0 += __shfl_xor_sync(0xffffffffu, s0, off);
            s1 += __shfl_xor_sync(0xffffffffu, s1, off);
        }

        if (lane == 0) {
            g_h[r0] = s0;
            if (r1 < N) g_h[r1] = s1;
        }
    }

    // degree histogram (sector-padded targets), overlaps the DRAM stream
    int stride = gridDim.x * blockDim.x;
    for (int i = tid; i < E; i += stride)
        atomicAdd(&g_deg8[(unsigned)dst[i] * PAD], 1.0f);
}

// ---------------------------------------------------------------------------
// K3: dinv = rsqrt(deg+1); ph = fp16(dinv*h); re-zero deg bins. 2 nodes/thread.
// ---------------------------------------------------------------------------
__global__ void k3_norm(int N) {
    int t = blockIdx.x * blockDim.x + threadIdx.x;
    int i0 = t * 2, i1 = i0 + 1;
    if (i0 < N) {
        float d0 = g_deg8[(unsigned)i0 * PAD];
        float d1 = (i1 < N) ? g_deg8[(unsigned)i1 * PAD] : 0.0f;
        float h0 = g_h[i0];
        float h1 = (i1 < N) ? g_h[i1] : 0.0f;

        g_deg8[(unsigned)i0 * PAD] = 0.0f;
        float v0 = rsqrtf(d0 + 1.0f);
        g_dinv[i0] = v0;
        g_ph[i0] = __float2half_rn(v0 * h0);

        if (i1 < N) {
            g_deg8[(unsigned)i1 * PAD] = 0.0f;
            float v1 = rsqrtf(d1 + 1.0f);
            g_dinv[i1] = v1;
            g_ph[i1] = __float2half_rn(v1 * h1);
        }
    }
}

// ---------------------------------------------------------------------------
// K4: persistent, one block/SM. Stage fp16 p-vector into SMEM (200KB), then
// grid-stride edges gathering from SMEM; atomics to sector-padded L2 bins.
// Measured at the LTS sector-traffic cap — keep as-is.
// ---------------------------------------------------------------------------
__global__ void __launch_bounds__(1024, 1)
k4_scatter_smem(const int* __restrict__ src,
                const int* __restrict__ dst, int N, int E) {
    extern __shared__ __half sph[];

    int n16 = (N * 2 + 15) / 16;   // uint4 count (MAXN padding: over-read safe)
    const uint4* gp4 = reinterpret_cast<const uint4*>(g_ph);
    uint4* sp4 = reinterpret_cast<uint4*>(sph);
    for (int i = threadIdx.x; i < n16; i += blockDim.x)
        sp4[i] = gp4[i];
    __syncthreads();

    int tid = blockIdx.x * blockDim.x + threadIdx.x;
    int stride = gridDim.x * blockDim.x;
    for (int i = tid; i < E; i += stride) {
        int s = src[i];
        int d = dst[i];
        atomicAdd(&g_acc8[(unsigned)d * PAD], __half2float(sph[s]));
    }
}

// fallback if N too large for SMEM staging
__global__ void k4_scatter_fallback(const int* __restrict__ src,
                                    const int* __restrict__ dst, int E) {
    int i = blockIdx.x * blockDim.x + threadIdx.x;
    int stride = gridDim.x * blockDim.x;
    for (; i < E; i += stride)
        atomicAdd(&g_acc8[(unsigned)dst[i] * PAD], __half2float(g_ph[src[i]]));
}

// ---------------------------------------------------------------------------
// K5: out = softplus(dinv*(acc + dinv*h) + b); re-zero acc bins. 2/thread.
// ---------------------------------------------------------------------------
__global__ void k5_epilogue(float* __restrict__ out,
                            const float* __restrict__ b, int N) {
    int t = blockIdx.x * blockDim.x + threadIdx.x;
    int i0 = t * 2, i1 = i0 + 1;
    if (i0 < N) {
        float bb = b[0];
        float a0 = g_acc8[(unsigned)i0 * PAD];
        float a1 = (i1 < N) ? g_acc8[(unsigned)i1 * PAD] : 0.0f;
        float h0 = g_h[i0];
        float h1 = (i1 < N) ? g_h[i1] : 0.0f;
        float q0 = g_dinv[i0];
        float q1 = (i1 < N) ? g_dinv[i1] : 0.0f;

        g_acc8[(unsigned)i0 * PAD] = 0.0f;
        float v0 = q0 * (a0 + q0 * h0) + bb;
        out[i0] = fmaxf(v0, 0.0f) + log1pf(expf(-fabsf(v0)));

        if (i1 < N) {
            g_acc8[(unsigned)i1 * PAD] = 0.0f;
            float v1 = q1 * (a1 + q1 * h1) + bb;
            out[i1] = fmaxf(v1, 0.0f) + log1pf(expf(-fabsf(v1)));
        }
    }
}

extern "C" void kernel_launch(void* const* d_in, const int* in_sizes, int n_in,
                              void* d_out, int out_size) {
    const float* x   = (const float*)d_in[0];
    const int*   ei  = (const int*)d_in[1];   // [2, E], int32
    const float* W   = (const float*)d_in[2];
    const float* b   = (const float*)d_in[3];
    float*       out = (float*)d_out;

    int C = in_sizes[2];            // 256
    int N = in_sizes[0] / C;        // 100000
    int E = in_sizes[1] / 2;        // 3200000

    const int* src = ei;
    const int* dst = ei + E;

    // K1 fused: 512 threads = 16 warps = 32 rows/block (2 rows/warp)
    {
        int rows_per_block = 32;
        int blocks = (N + rows_per_block - 1) / rows_per_block;
        k1_fused<<<blocks, 512>>>(x, W, dst, N, C, E);
    }
    // K3: 2 nodes/thread
    {
        int threads = 256;
        int work = (N + 1) / 2;
        int blocks = (work + threads - 1) / threads;
        k3_norm<<<blocks, threads>>>(N);
    }
    // K4: persistent SMEM-staged scatter (one block per SM)
    {
        int sm_count = 148;
        cudaDeviceGetAttribute(&sm_count, cudaDevAttrMultiProcessorCount, 0);
        size_t smem_bytes = ((size_t)N * 2 + 15) & ~(size_t)15;
        static int attr_set = 0;
        if (!attr_set) {
            cudaFuncSetAttribute(k4_scatter_smem,
                                 cudaFuncAttributeMaxDynamicSharedMemorySize,
                                 227 * 1024);
            attr_set = 1;
        }
        if (smem_bytes <= 227 * 1024) {
            k4_scatter_smem<<<sm_count, 1024, smem_bytes>>>(src, dst, N, E);
        } else {
            int threads = 256;
            int blocks = (E + threads - 1) / threads;
            if (blocks > 65535) blocks = 65535;
            k4_scatter_fallback<<<blocks, threads>>>(src, dst, E);
        }
    }
    // K5: 2 nodes/thread
    {
        int threads = 256;
        int work = (N + 1) / 2;
        int blocks = (work + threads - 1) / threads;
        k5_epilogue<<<blocks, threads>>>(out, b, N);
    }
}